// round 11
// baseline (speedup 1.0000x reference)
#include <cuda_runtime.h>
#include <cstddef>
#include <cstdint>

// LimbLength: out[b][k] = || in[b][k][:] - in[b][conn[k]][:] ||_2
// R4 per-tile body (best measured) + PERSISTENT grid (148 SMs x 9 blocks):
// each warp loops over ~6 tiles of 32 samples, eliminating the 5.87-wave
// launch structure (wave transitions + ragged tail). Per-warp tiles
// (5760 B = 45 x 128 B, sector-aligned), no block barriers, cp.async.cg
// staging, compute from smem (odd strides -> conflict-free), smem reused
// for coalesced float4 output stores.

#define TPB 128
#define WARPS 4
#define SPW 32                       // samples per tile
#define FPW (SPW * 45)               // 1440 floats = 5760 B per warp
#define GRID 1332                    // 148 SMs * 9 blocks (one wave)

__device__ __forceinline__ float fast_sqrt(float x) {
    float r;
    asm("sqrt.approx.f32 %0, %1;" : "=f"(r) : "f"(x));
    return r;
}

__device__ __forceinline__ void cp_async16(uint32_t smem_addr, const void* gptr) {
    asm volatile("cp.async.cg.shared.global [%0], [%1], 16;" ::
                 "r"(smem_addr), "l"(gptr));
}

__global__ void __launch_bounds__(TPB, 9)
limb_length_kernel(const float* __restrict__ in, float* __restrict__ out, int B) {
    __shared__ __align__(16) float s_buf[WARPS * FPW];   // 23040 B

    const int w    = threadIdx.x >> 5;
    const int lane = threadIdx.x & 31;
    float* sw = s_buf + w * FPW;

    const int ntiles = (B + SPW - 1) / SPW;
    const int nwarps = GRID * WARPS;

    for (int tile = blockIdx.x * WARPS + w; tile < ntiles; tile += nwarps) {
        const int sbase = tile * SPW;
        const int nsamp = min(SPW, B - sbase);

        // ---- stage gmem -> smem (per-warp, coalesced, async) ----
        if (nsamp == SPW) {
            const char* gsrc = reinterpret_cast<const char*>(in + (size_t)sbase * 45);
            const uint32_t sdst = (uint32_t)__cvta_generic_to_shared(sw);
            #pragma unroll
            for (int j = 0; j < 11; j++) {
                const int i = lane + 32 * j;
                cp_async16(sdst + i * 16, gsrc + i * 16);
            }
            if (lane < 8) {
                const int i = lane + 352;
                cp_async16(sdst + i * 16, gsrc + i * 16);
            }
            asm volatile("cp.async.commit_group;\n"
                         "cp.async.wait_group 0;" ::: "memory");
        } else {
            const size_t goff = (size_t)sbase * 45;
            for (int i = lane; i < nsamp * 45; i += 32) sw[i] = in[goff + i];
        }
        __syncwarp();

        // ---- compute: one sample per lane, straight from smem ----
        float r[15];
        if (lane < nsamp) {
            const float* __restrict__ p = sw + lane * 45;   // stride 45 odd -> conflict-free
            const int conn[15] = {0, 0, 1, 1, 1, 3, 4, 5, 6, 2, 2, 9, 10, 11, 12};
            #pragma unroll
            for (int k = 0; k < 15; k++) {
                const int c = conn[k];                      // compile-time constant
                const float dx = p[3 * k + 0] - p[3 * c + 0];
                const float dy = p[3 * k + 1] - p[3 * c + 1];
                const float dz = p[3 * k + 2] - p[3 * c + 2];
                r[k] = fast_sqrt(dx * dx + dy * dy + dz * dz);
            }
        }
        __syncwarp();                    // all smem reads done before overwrite

        if (lane < nsamp) {
            float* q = sw + lane * 15;                      // stride 15 odd -> conflict-free
            #pragma unroll
            for (int k = 0; k < 15; k++) q[k] = r[k];
        }
        __syncwarp();

        // ---- coalesced store: smem -> gmem (nsamp*15 floats) ----
        {
            const size_t goff = (size_t)sbase * 15;
            const int nfloat = nsamp * 15;
            const int n4 = nfloat >> 2;                     // 120 when full
            float4* __restrict__ g4 = reinterpret_cast<float4*>(out + goff);
            const float4* s4 = reinterpret_cast<const float4*>(sw);
            #pragma unroll 4
            for (int i = lane; i < n4; i += 32) g4[i] = s4[i];
            for (int i = (n4 << 2) + lane; i < nfloat; i += 32)
                out[goff + i] = sw[i];
        }
        __syncwarp();   // STG sources consumed; safe to overwrite sw next iter
    }
}

extern "C" void kernel_launch(void* const* d_in, const int* in_sizes, int n_in,
                              void* d_out, int out_size) {
    const float* in = (const float*)d_in[0];
    float* out = (float*)d_out;
    const int B = in_sizes[0] / 45;
    limb_length_kernel<<<GRID, TPB>>>(in, out, B);
}

// round 12
// speedup vs baseline: 1.1034x; 1.1034x over previous
#include <cuda_runtime.h>
#include <cstddef>
#include <cstdint>

// LimbLength: out[b][k] = || in[b][k][:] - in[b][conn[k]][:] ||_2
// FINAL (R4 structure, best measured; all perturbations regressed):
// per-WARP tiles of 32 samples (5760 B = 45 x 128 B -> every tile base
// 128B-sector-aligned), no block barriers (only __syncwarp), cp.async.cg
// gmem->smem staging, compute from smem (odd strides 45/15 ->
// bank-conflict-free), smem reused for coalesced float4 output stores.
// 4 warps/block, 23040 B smem -> 9 blocks/SM = 36 warps/SM. Block
// retirement provides cross-tile pipelining (fresh blocks' loads overlap
// resident blocks' compute/store).

#define TPB 128
#define WARPS 4
#define SPW 32                      // samples per warp
#define FPW (SPW * 45)              // 1440 floats = 5760 B per warp

__device__ __forceinline__ float fast_sqrt(float x) {
    float r;
    asm("sqrt.approx.f32 %0, %1;" : "=f"(r) : "f"(x));
    return r;
}

__device__ __forceinline__ void cp_async16(uint32_t smem_addr, const void* gptr) {
    asm volatile("cp.async.cg.shared.global [%0], [%1], 16;" ::
                 "r"(smem_addr), "l"(gptr));
}

__global__ void __launch_bounds__(TPB, 9)
limb_length_kernel(const float* __restrict__ in, float* __restrict__ out, int B) {
    __shared__ __align__(16) float s_buf[WARPS * FPW];   // 23040 B

    const int w    = threadIdx.x >> 5;
    const int lane = threadIdx.x & 31;
    const int sbase = (blockIdx.x * WARPS + w) * SPW;    // first sample of this warp
    if (sbase >= B) return;                              // warp-uniform exit
    const int nsamp = min(SPW, B - sbase);

    float* sw = s_buf + w * FPW;

    // ---- stage gmem -> smem (per-warp, coalesced, async) ----
    if (nsamp == SPW) {
        // 1440 floats = 360 float4: 11 full rounds + 8 lanes
        const char* gsrc = reinterpret_cast<const char*>(in + (size_t)sbase * 45);
        uint32_t sdst = (uint32_t)__cvta_generic_to_shared(sw);
        #pragma unroll
        for (int j = 0; j < 11; j++) {
            const int i = lane + 32 * j;
            cp_async16(sdst + i * 16, gsrc + i * 16);
        }
        if (lane < 8) {
            const int i = lane + 352;
            cp_async16(sdst + i * 16, gsrc + i * 16);
        }
        asm volatile("cp.async.commit_group;\n"
                     "cp.async.wait_group 0;" ::: "memory");
    } else {
        const size_t goff = (size_t)sbase * 45;
        for (int i = lane; i < nsamp * 45; i += 32) sw[i] = in[goff + i];
    }
    __syncwarp();

    // ---- compute: one sample per lane, straight from smem ----
    float r[15];
    if (lane < nsamp) {
        const float* __restrict__ p = sw + lane * 45;    // stride 45 odd -> conflict-free
        const int conn[15] = {0, 0, 1, 1, 1, 3, 4, 5, 6, 2, 2, 9, 10, 11, 12};
        #pragma unroll
        for (int k = 0; k < 15; k++) {
            const int c = conn[k];                       // compile-time constant
            const float dx = p[3 * k + 0] - p[3 * c + 0];
            const float dy = p[3 * k + 1] - p[3 * c + 1];
            const float dz = p[3 * k + 2] - p[3 * c + 2];
            r[k] = fast_sqrt(dx * dx + dy * dy + dz * dz);
        }
    }
    __syncwarp();                    // all smem reads done before overwrite

    if (lane < nsamp) {
        float* q = sw + lane * 15;                       // stride 15 odd -> conflict-free
        #pragma unroll
        for (int k = 0; k < 15; k++) q[k] = r[k];
    }
    __syncwarp();

    // ---- coalesced store: smem -> gmem (nsamp*15 floats) ----
    {
        const size_t goff = (size_t)sbase * 15;
        const int nfloat = nsamp * 15;
        const int n4 = nfloat >> 2;                      // 120 when full
        float4* __restrict__ g4 = reinterpret_cast<float4*>(out + goff);
        const float4* s4 = reinterpret_cast<const float4*>(sw);
        #pragma unroll 4
        for (int i = lane; i < n4; i += 32) g4[i] = s4[i];
        for (int i = (n4 << 2) + lane; i < nfloat; i += 32)
            out[goff + i] = sw[i];
    }
}

extern "C" void kernel_launch(void* const* d_in, const int* in_sizes, int n_in,
                              void* d_out, int out_size) {
    const float* in = (const float*)d_in[0];
    float* out = (float*)d_out;
    const int B = in_sizes[0] / 45;
    const int spb = WARPS * SPW;     // 128 samples per block
    const int grid = (B + spb - 1) / spb;
    limb_length_kernel<<<grid, TPB>>>(in, out, B);
}